// round 11
// baseline (speedup 1.0000x reference)
#include <cuda_runtime.h>
#include <cstdint>

// Problem constants
#define Bv 8
#define Vv 256
#define Hv 128
#define ROWS (Bv*Vv)          // 2048
#define H4 (Hv/4)             // 32 float4 per row

typedef unsigned long long ull;

// Intermediates (device globals; no allocation allowed)
__device__ float g_h0[ROWS*Hv];                 // silu(h @ W_pre + b_pre)
__device__ float g_sk[ROWS*Hv];                 // silu(h @ W_skip + b_skip)
__device__ float g_part[2*ROWS*Hv];             // neigh partial maxes (2 j-halves)

__device__ __forceinline__ float silu_f(float x) {
    return x * (1.0f / (1.0f + __expf(-x)));
}

__device__ __forceinline__ void cp16(uint32_t dst, const void* src) {
    asm volatile("cp.async.cg.shared.global [%0], [%1], 16;" :: "r"(dst), "l"(src));
}
__device__ __forceinline__ void cp_commit() {
    asm volatile("cp.async.commit_group;");
}

__device__ __forceinline__ ull ffma2(ull a, ull b, ull c) {
    ull d;
    asm("fma.rn.f32x2 %0, %1, %2, %3;" : "=l"(d) : "l"(a), "l"(b), "l"(c));
    return d;
}
__device__ __forceinline__ ull pack2(float x, float y) {
    ull d; asm("mov.b64 %0, {%1, %2};" : "=l"(d) : "f"(x), "f"(y)); return d;
}
__device__ __forceinline__ float2 unpack2(ull v) {
    float2 r; asm("mov.b64 {%0, %1}, %2;" : "=f"(r.x), "=f"(r.y) : "l"(v)); return r;
}

// ---------------------------------------------------------------------------
// Kernel A: h0 = silu(h @ W_pre + b_pre), sk = silu(h @ W_skip + b_skip)
// 2-D tiled: 512 blocks (128 row-tiles x 4 col-tiles) x 128 threads.
// (frozen from R9/R10 best)
// ---------------------------------------------------------------------------
__global__ void __launch_bounds__(128) pre_kernel(
    const float* __restrict__ h,
    const float* __restrict__ Wpre,  const float* __restrict__ bpre,
    const float* __restrict__ Wskip, const float* __restrict__ bskip)
{
    __shared__ float sWA[Hv * 32];       // 16 KB : sWA[k][c]
    __shared__ float sWB[Hv * 32];       // 16 KB
    __shared__ float hT[Hv * 16];        // 8 KB  : hT[k][r]

    const int tid  = threadIdx.x;
    const int c    = tid & 31;
    const int rg   = tid >> 5;           // 0..3 (4-row group)
    const int rowT = blockIdx.x >> 2;
    const int colT = blockIdx.x & 3;
    const int row0 = rowT * 16;
    const int col0 = colT * 32;

    const float4* WAg = (const float4*)Wpre;
    const float4* WBg = (const float4*)Wskip;
#pragma unroll
    for (int r = 0; r < 8; r++) {
        const int x = r * 128 + tid;           // x = k*8 + c4
        const int src = (x >> 3) * 32 + colT * 8 + (x & 7);
        ((float4*)sWA)[x] = WAg[src];
        ((float4*)sWB)[x] = WBg[src];
    }

    const float4* h4 = (const float4*)h;
#pragma unroll
    for (int x = tid; x < 512; x += 128) {
        const int rr = x & 15, k4 = x >> 4;
        float4 v = h4[(row0 + rr) * H4 + k4];
        hT[(k4 * 4 + 0) * 16 + rr] = v.x;
        hT[(k4 * 4 + 1) * 16 + rr] = v.y;
        hT[(k4 * 4 + 2) * 16 + rr] = v.z;
        hT[(k4 * 4 + 3) * 16 + rr] = v.w;
    }
    __syncthreads();

    ull accA0, accA1, accB0, accB1;
    {
        const float bA = bpre[col0 + c], bB = bskip[col0 + c];
        accA0 = pack2(bA, bA); accA1 = accA0;
        accB0 = pack2(bB, bB); accB1 = accB0;
    }

#pragma unroll 16
    for (int k = 0; k < Hv; k++) {
        ulonglong2 hv = *(const ulonglong2*)&hT[k * 16 + 4 * rg];  // 4 rows, bcast
        const float wa = sWA[k * 32 + c];
        const float wb = sWB[k * 32 + c];
        const ull wa2 = pack2(wa, wa);
        const ull wb2 = pack2(wb, wb);
        accA0 = ffma2(hv.x, wa2, accA0);
        accA1 = ffma2(hv.y, wa2, accA1);
        accB0 = ffma2(hv.x, wb2, accB0);
        accB1 = ffma2(hv.y, wb2, accB1);
    }

    {
        float2 a0 = unpack2(accA0), a1 = unpack2(accA1);
        float2 b0 = unpack2(accB0), b1 = unpack2(accB1);
        const int row = row0 + 4 * rg;
        const int col = col0 + c;
        g_h0[(row + 0) * Hv + col] = silu_f(a0.x);
        g_h0[(row + 1) * Hv + col] = silu_f(a0.y);
        g_h0[(row + 2) * Hv + col] = silu_f(a1.x);
        g_h0[(row + 3) * Hv + col] = silu_f(a1.y);
        g_sk[(row + 0) * Hv + col] = silu_f(b0.x);
        g_sk[(row + 1) * Hv + col] = silu_f(b0.y);
        g_sk[(row + 2) * Hv + col] = silu_f(b1.x);
        g_sk[(row + 3) * Hv + col] = silu_f(b1.y);
    }
}

// ---------------------------------------------------------------------------
// Kernel B (dominant): partial neigh max over a 128-wide j-half.
// SYNC-FREE version: the ENTIRE h0 j-half (128 j x 128 h = 64 KB) is staged
// once with a single barrier. Each warp then compacts its row's unmasked j
// indices via ballot and streams them branch-free, 4 e-rows per iteration
// (one int4 LDS for indices, 4 independent __ldcs LDG.128s). No barriers in
// the stream -> load imbalance only at kernel tail, smoothed by 3+ blocks/SM.
// ---------------------------------------------------------------------------
__global__ void __launch_bounds__(256) agg_kernel(
    const float* __restrict__ e,
    const int*   __restrict__ graph)
{
    __shared__ float4 h0s[128 * H4];     // 64 KB : h0s[j][hq]
    __shared__ int    jlist[8][128];     // 4 KB

    const int tid  = threadIdx.x;
    const int hq   = tid & 31;           // float4 index in H == lane
    const int isub = tid >> 5;           // 0..7 == warp index
    const int b    = blockIdx.x >> 6;
    const int rem  = blockIdx.x & 63;
    const int i0   = (rem >> 1) * 8;
    const int jh   = rem & 1;
    const int j0   = jh * 128;
    const int i    = i0 + isub;

    // Stage the full h0 j-half: 4096 float4, 16/thread via cp.async.
    const float4* H0 = (const float4*)g_h0 + (b * Vv + j0) * H4;
    const uint32_t sb = (uint32_t)__cvta_generic_to_shared(&h0s[0]);
#pragma unroll
    for (int r = 0; r < 16; r++) {
        const int x = r * 256 + tid;
        cp16(sb + x * 16, (const void*)(H0 + x));
    }
    cp_commit();

    // Build this warp's compacted unmasked-j list (ballot ranking).
    const int* grow = graph + (size_t)(b * Vv + i) * Vv + j0;
    int cnt = 0;
#pragma unroll
    for (int g = 0; g < 4; g++) {
        const int j = g * 32 + hq;
        const bool un = (grow[j] == 0);
        const unsigned m = __ballot_sync(0xffffffffu, un);
        if (un) {
            const int rank = __popc(m & ((1u << hq) - 1u));
            jlist[isub][cnt + rank] = j;
        }
        cnt += __popc(m);
    }

    asm volatile("cp.async.wait_group 0;");
    __syncthreads();

    const float4* Ep = (const float4*)e + ((size_t)(b * Vv + i) * Vv + j0) * H4 + hq;
    const float NEG_INF = __int_as_float(0xff800000);
    float4 acc = make_float4(NEG_INF, NEG_INF, NEG_INF, NEG_INF);

    int t = 0;
    for (; t + 4 <= cnt; t += 4) {
        int4 j4 = *(const int4*)&jlist[isub][t];     // one LDS.128, broadcast
        float4 e0 = __ldcs(&Ep[(size_t)j4.x * H4]);
        float4 e1 = __ldcs(&Ep[(size_t)j4.y * H4]);
        float4 e2 = __ldcs(&Ep[(size_t)j4.z * H4]);
        float4 e3 = __ldcs(&Ep[(size_t)j4.w * H4]);
        float4 h0v = h0s[j4.x * H4 + hq];
        float4 h1v = h0s[j4.y * H4 + hq];
        float4 h2v = h0s[j4.z * H4 + hq];
        float4 h3v = h0s[j4.w * H4 + hq];
        acc.x = fmaxf(acc.x, e0.x * h0v.x); acc.y = fmaxf(acc.y, e0.y * h0v.y);
        acc.z = fmaxf(acc.z, e0.z * h0v.z); acc.w = fmaxf(acc.w, e0.w * h0v.w);
        acc.x = fmaxf(acc.x, e1.x * h1v.x); acc.y = fmaxf(acc.y, e1.y * h1v.y);
        acc.z = fmaxf(acc.z, e1.z * h1v.z); acc.w = fmaxf(acc.w, e1.w * h1v.w);
        acc.x = fmaxf(acc.x, e2.x * h2v.x); acc.y = fmaxf(acc.y, e2.y * h2v.y);
        acc.z = fmaxf(acc.z, e2.z * h2v.z); acc.w = fmaxf(acc.w, e2.w * h2v.w);
        acc.x = fmaxf(acc.x, e3.x * h3v.x); acc.y = fmaxf(acc.y, e3.y * h3v.y);
        acc.z = fmaxf(acc.z, e3.z * h3v.z); acc.w = fmaxf(acc.w, e3.w * h3v.w);
    }
    for (; t < cnt; t++) {
        const int j = jlist[isub][t];
        float4 ev = __ldcs(&Ep[(size_t)j * H4]);
        float4 hv = h0s[j * H4 + hq];
        acc.x = fmaxf(acc.x, ev.x * hv.x);
        acc.y = fmaxf(acc.y, ev.y * hv.y);
        acc.z = fmaxf(acc.z, ev.z * hv.z);
        acc.w = fmaxf(acc.w, ev.w * hv.w);
    }

    if (cnt < 128) {                      // masked rows contribute exactly 0
        acc.x = fmaxf(acc.x, 0.0f);
        acc.y = fmaxf(acc.y, 0.0f);
        acc.z = fmaxf(acc.z, 0.0f);
        acc.w = fmaxf(acc.w, 0.0f);
    }

    ((float4*)g_part)[((size_t)jh * ROWS + b * Vv + i) * H4 + hq] = acc;
}

// ---------------------------------------------------------------------------
// Kernel C: out = silu( sk + silu([h0,neigh] @ W_post + b_post) )
// 2-D tiled: 512 blocks (128 row-tiles x 4 col-tiles) x 128 threads.
// (frozen from R9/R10 best)
// ---------------------------------------------------------------------------
extern __shared__ float s_dyn[];

__global__ void __launch_bounds__(128) post_kernel(
    const float* __restrict__ Wpost, const float* __restrict__ bpost,
    float* __restrict__ out)
{
    float* sW = s_dyn;                    // sW[k][c], 256 x 32
    float* aT = s_dyn + 2 * Hv * 32;      // aT[k][r], 256 x 16

    const int tid  = threadIdx.x;
    const int c    = tid & 31;
    const int rg   = tid >> 5;            // 0..3
    const int rowT = blockIdx.x >> 2;
    const int colT = blockIdx.x & 3;
    const int row0 = rowT * 16;
    const int col0 = colT * 32;

    const float4* Wg = (const float4*)Wpost;
#pragma unroll
    for (int r = 0; r < 16; r++) {
        const int x = r * 128 + tid;           // x = k*8 + c4
        ((float4*)sW)[x] = Wg[(x >> 3) * 32 + colT * 8 + (x & 7)];
    }

    const float4* h04 = (const float4*)g_h0;
    const float4* gp  = (const float4*)g_part;
#pragma unroll
    for (int x = tid; x < 512; x += 128) {
        const int rr = x & 15, k4 = x >> 4;
        float4 v = h04[(row0 + rr) * H4 + k4];
        aT[(k4 * 4 + 0) * 16 + rr] = v.x;
        aT[(k4 * 4 + 1) * 16 + rr] = v.y;
        aT[(k4 * 4 + 2) * 16 + rr] = v.z;
        aT[(k4 * 4 + 3) * 16 + rr] = v.w;
        float4 p0 = gp[(row0 + rr) * H4 + k4];
        float4 p1 = gp[(size_t)ROWS * H4 + (row0 + rr) * H4 + k4];
        aT[(Hv + k4 * 4 + 0) * 16 + rr] = fmaxf(p0.x, p1.x);
        aT[(Hv + k4 * 4 + 1) * 16 + rr] = fmaxf(p0.y, p1.y);
        aT[(Hv + k4 * 4 + 2) * 16 + rr] = fmaxf(p0.z, p1.z);
        aT[(Hv + k4 * 4 + 3) * 16 + rr] = fmaxf(p0.w, p1.w);
    }
    __syncthreads();

    ull acc0, acc1;
    {
        const float bP = bpost[col0 + c];
        acc0 = pack2(bP, bP);
        acc1 = pack2(0.f, 0.f);
    }

#pragma unroll 16
    for (int k = 0; k < 2 * Hv; k++) {
        ulonglong2 av = *(const ulonglong2*)&aT[k * 16 + 4 * rg];  // 4 rows, bcast
        const float w = sW[k * 32 + c];
        const ull w2 = pack2(w, w);
        acc0 = ffma2(av.x, w2, acc0);
        acc1 = ffma2(av.y, w2, acc1);
    }

    {
        float2 v0 = unpack2(acc0), v1 = unpack2(acc1);
        const int row = row0 + 4 * rg;
        const int col = col0 + c;
        out[(row + 0) * Hv + col] = silu_f(g_sk[(row + 0) * Hv + col] + silu_f(v0.x));
        out[(row + 1) * Hv + col] = silu_f(g_sk[(row + 1) * Hv + col] + silu_f(v0.y));
        out[(row + 2) * Hv + col] = silu_f(g_sk[(row + 2) * Hv + col] + silu_f(v1.x));
        out[(row + 3) * Hv + col] = silu_f(g_sk[(row + 3) * Hv + col] + silu_f(v1.y));
    }
}

// ---------------------------------------------------------------------------
extern "C" void kernel_launch(void* const* d_in, const int* in_sizes, int n_in,
                              void* d_out, int out_size)
{
    const float* h     = (const float*)d_in[0];
    const float* e     = (const float*)d_in[1];
    const int*   graph = (const int*)  d_in[2];
    const float* Wpre  = (const float*)d_in[3];
    const float* bpre  = (const float*)d_in[4];
    const float* Wpost = (const float*)d_in[5];
    const float* bpost = (const float*)d_in[6];
    const float* Wskip = (const float*)d_in[7];
    const float* bskip = (const float*)d_in[8];
    float* out = (float*)d_out;

    const int postSmem = (2 * Hv * 32 + 2 * Hv * 16) * 4;     // 48 KB
    cudaFuncSetAttribute(post_kernel, cudaFuncAttributeMaxDynamicSharedMemorySize, postSmem);

    pre_kernel<<<512, 128>>>(h, Wpre, bpre, Wskip, bskip);
    agg_kernel<<<(ROWS / 8) * 2, 256>>>(e, graph);
    post_kernel<<<512, 128, postSmem>>>(Wpost, bpost, out);
}

// round 12
// speedup vs baseline: 1.1466x; 1.1466x over previous
#include <cuda_runtime.h>
#include <cstdint>

// Problem constants
#define Bv 8
#define Vv 256
#define Hv 128
#define ROWS (Bv*Vv)          // 2048
#define H4 (Hv/4)             // 32 float4 per row

typedef unsigned long long ull;

// Intermediates (device globals; no allocation allowed)
__device__ float g_h0[ROWS*Hv];                 // silu(h @ W_pre + b_pre)
__device__ float g_sk[ROWS*Hv];                 // silu(h @ W_skip + b_skip)
__device__ float g_part[2*ROWS*Hv];             // neigh partial maxes (2 j-halves)

__device__ __forceinline__ float silu_f(float x) {
    return x * (1.0f / (1.0f + __expf(-x)));
}

__device__ __forceinline__ void cp16(uint32_t dst, const void* src) {
    asm volatile("cp.async.cg.shared.global [%0], [%1], 16;" :: "r"(dst), "l"(src));
}
__device__ __forceinline__ void cp_commit() {
    asm volatile("cp.async.commit_group;");
}

__device__ __forceinline__ ull ffma2(ull a, ull b, ull c) {
    ull d;
    asm("fma.rn.f32x2 %0, %1, %2, %3;" : "=l"(d) : "l"(a), "l"(b), "l"(c));
    return d;
}
__device__ __forceinline__ ull pack2(float x, float y) {
    ull d; asm("mov.b64 %0, {%1, %2};" : "=l"(d) : "f"(x), "f"(y)); return d;
}
__device__ __forceinline__ float2 unpack2(ull v) {
    float2 r; asm("mov.b64 {%0, %1}, %2;" : "=f"(r.x), "=f"(r.y) : "l"(v)); return r;
}

// ---------------------------------------------------------------------------
// Kernel A: h0 = silu(h @ W_pre + b_pre), sk = silu(h @ W_skip + b_skip)
// 2-D tiled: 512 blocks (128 row-tiles x 4 col-tiles) x 128 threads. (frozen)
// ---------------------------------------------------------------------------
__global__ void __launch_bounds__(128) pre_kernel(
    const float* __restrict__ h,
    const float* __restrict__ Wpre,  const float* __restrict__ bpre,
    const float* __restrict__ Wskip, const float* __restrict__ bskip)
{
    __shared__ float sWA[Hv * 32];       // 16 KB : sWA[k][c]
    __shared__ float sWB[Hv * 32];       // 16 KB
    __shared__ float hT[Hv * 16];        // 8 KB  : hT[k][r]

    const int tid  = threadIdx.x;
    const int c    = tid & 31;
    const int rg   = tid >> 5;           // 0..3 (4-row group)
    const int rowT = blockIdx.x >> 2;
    const int colT = blockIdx.x & 3;
    const int row0 = rowT * 16;
    const int col0 = colT * 32;

    const float4* WAg = (const float4*)Wpre;
    const float4* WBg = (const float4*)Wskip;
#pragma unroll
    for (int r = 0; r < 8; r++) {
        const int x = r * 128 + tid;           // x = k*8 + c4
        const int src = (x >> 3) * 32 + colT * 8 + (x & 7);
        ((float4*)sWA)[x] = WAg[src];
        ((float4*)sWB)[x] = WBg[src];
    }

    const float4* h4 = (const float4*)h;
#pragma unroll
    for (int x = tid; x < 512; x += 128) {
        const int rr = x & 15, k4 = x >> 4;
        float4 v = h4[(row0 + rr) * H4 + k4];
        hT[(k4 * 4 + 0) * 16 + rr] = v.x;
        hT[(k4 * 4 + 1) * 16 + rr] = v.y;
        hT[(k4 * 4 + 2) * 16 + rr] = v.z;
        hT[(k4 * 4 + 3) * 16 + rr] = v.w;
    }
    __syncthreads();

    ull accA0, accA1, accB0, accB1;
    {
        const float bA = bpre[col0 + c], bB = bskip[col0 + c];
        accA0 = pack2(bA, bA); accA1 = accA0;
        accB0 = pack2(bB, bB); accB1 = accB0;
    }

#pragma unroll 16
    for (int k = 0; k < Hv; k++) {
        ulonglong2 hv = *(const ulonglong2*)&hT[k * 16 + 4 * rg];  // 4 rows, bcast
        const float wa = sWA[k * 32 + c];
        const float wb = sWB[k * 32 + c];
        const ull wa2 = pack2(wa, wa);
        const ull wb2 = pack2(wb, wb);
        accA0 = ffma2(hv.x, wa2, accA0);
        accA1 = ffma2(hv.y, wa2, accA1);
        accB0 = ffma2(hv.x, wb2, accB0);
        accB1 = ffma2(hv.y, wb2, accB1);
    }

    {
        float2 a0 = unpack2(accA0), a1 = unpack2(accA1);
        float2 b0 = unpack2(accB0), b1 = unpack2(accB1);
        const int row = row0 + 4 * rg;
        const int col = col0 + c;
        g_h0[(row + 0) * Hv + col] = silu_f(a0.x);
        g_h0[(row + 1) * Hv + col] = silu_f(a0.y);
        g_h0[(row + 2) * Hv + col] = silu_f(a1.x);
        g_h0[(row + 3) * Hv + col] = silu_f(a1.y);
        g_sk[(row + 0) * Hv + col] = silu_f(b0.x);
        g_sk[(row + 1) * Hv + col] = silu_f(b0.y);
        g_sk[(row + 2) * Hv + col] = silu_f(b1.x);
        g_sk[(row + 3) * Hv + col] = silu_f(b1.y);
    }
}

// ---------------------------------------------------------------------------
// Kernel B (dominant): partial neigh max over a 128-wide j-half.
// v3: 512 blocks x 256 thr, 36 KB smem -> ALL resident (single wave).
// h0 staged in TWO 64-j mega-chunks through ONE 32 KB buffer (2 barriers
// instead of 4). Per-warp unmasked-j lists compacted once via ballot into
// two per-chunk arrays (int4-aligned), then streamed branch-free 4 rows per
// iteration with independent __ldcs LDG.128s.
// ---------------------------------------------------------------------------
__global__ void __launch_bounds__(256) agg_kernel(
    const float* __restrict__ e,
    const int*   __restrict__ graph)
{
    __shared__ float4 h0s[64 * H4];      // 32 KB : h0s[jj][hq], jj in [0,64)
    __shared__ int    jl0[8][64];        // 2 KB  : unmasked j in [0,64)
    __shared__ int    jl1[8][64];        // 2 KB  : unmasked j in [64,128)

    const int tid  = threadIdx.x;
    const int hq   = tid & 31;           // float4 index in H == lane
    const int isub = tid >> 5;           // 0..7 == warp index
    const int b    = blockIdx.x >> 6;
    const int rem  = blockIdx.x & 63;
    const int i0   = (rem >> 1) * 8;
    const int jh   = rem & 1;
    const int j0   = jh * 128;
    const int i    = i0 + isub;

    const float4* H0 = (const float4*)g_h0 + (b * Vv + j0) * H4;
    const uint32_t sb = (uint32_t)__cvta_generic_to_shared(&h0s[0]);

    // Stage mega-chunk 0 (j 0..63): 2048 float4, 8/thread via cp.async.
#pragma unroll
    for (int r = 0; r < 8; r++) {
        const int x = r * 256 + tid;
        cp16(sb + x * 16, (const void*)(H0 + x));
    }
    cp_commit();

    // Build this warp's compacted unmasked-j lists (ballot ranking).
    const int* grow = graph + (size_t)(b * Vv + i) * Vv + j0;
    int c0 = 0, c1 = 0;
#pragma unroll
    for (int g = 0; g < 4; g++) {
        const int j = g * 32 + hq;
        const bool un = (grow[j] == 0);
        const unsigned m = __ballot_sync(0xffffffffu, un);
        const int rank = __popc(m & ((1u << hq) - 1u));
        if (g < 2) {
            if (un) jl0[isub][c0 + rank] = j;
            c0 += __popc(m);
        } else {
            if (un) jl1[isub][c1 + rank] = j - 64;
            c1 += __popc(m);
        }
    }

    asm volatile("cp.async.wait_group 0;");
    __syncthreads();

    const float4* Ep = (const float4*)e + ((size_t)(b * Vv + i) * Vv + j0) * H4 + hq;
    const float NEG_INF = __int_as_float(0xff800000);
    float4 acc = make_float4(NEG_INF, NEG_INF, NEG_INF, NEG_INF);

    // ---- mega-chunk 0 ----
    {
        const int* jl = jl0[isub];
        int t = 0;
        for (; t + 4 <= c0; t += 4) {
            int4 j4 = *(const int4*)&jl[t];          // aligned LDS.128
            float4 e0 = __ldcs(&Ep[(size_t)j4.x * H4]);
            float4 e1 = __ldcs(&Ep[(size_t)j4.y * H4]);
            float4 e2 = __ldcs(&Ep[(size_t)j4.z * H4]);
            float4 e3 = __ldcs(&Ep[(size_t)j4.w * H4]);
            float4 h0v = h0s[j4.x * H4 + hq];
            float4 h1v = h0s[j4.y * H4 + hq];
            float4 h2v = h0s[j4.z * H4 + hq];
            float4 h3v = h0s[j4.w * H4 + hq];
            acc.x = fmaxf(acc.x, e0.x * h0v.x); acc.y = fmaxf(acc.y, e0.y * h0v.y);
            acc.z = fmaxf(acc.z, e0.z * h0v.z); acc.w = fmaxf(acc.w, e0.w * h0v.w);
            acc.x = fmaxf(acc.x, e1.x * h1v.x); acc.y = fmaxf(acc.y, e1.y * h1v.y);
            acc.z = fmaxf(acc.z, e1.z * h1v.z); acc.w = fmaxf(acc.w, e1.w * h1v.w);
            acc.x = fmaxf(acc.x, e2.x * h2v.x); acc.y = fmaxf(acc.y, e2.y * h2v.y);
            acc.z = fmaxf(acc.z, e2.z * h2v.z); acc.w = fmaxf(acc.w, e2.w * h2v.w);
            acc.x = fmaxf(acc.x, e3.x * h3v.x); acc.y = fmaxf(acc.y, e3.y * h3v.y);
            acc.z = fmaxf(acc.z, e3.z * h3v.z); acc.w = fmaxf(acc.w, e3.w * h3v.w);
        }
        for (; t < c0; t++) {
            const int j = jl[t];
            float4 ev = __ldcs(&Ep[(size_t)j * H4]);
            float4 hv = h0s[j * H4 + hq];
            acc.x = fmaxf(acc.x, ev.x * hv.x);
            acc.y = fmaxf(acc.y, ev.y * hv.y);
            acc.z = fmaxf(acc.z, ev.z * hv.z);
            acc.w = fmaxf(acc.w, ev.w * hv.w);
        }
    }

    // ---- restage buffer with mega-chunk 1 (j 64..127) ----
    __syncthreads();
#pragma unroll
    for (int r = 0; r < 8; r++) {
        const int x = r * 256 + tid;
        cp16(sb + x * 16, (const void*)(H0 + 2048 + x));
    }
    cp_commit();
    asm volatile("cp.async.wait_group 0;");
    __syncthreads();

    // ---- mega-chunk 1 ----
    {
        const float4* Ep1 = Ep + 64 * H4;
        const int* jl = jl1[isub];
        int t = 0;
        for (; t + 4 <= c1; t += 4) {
            int4 j4 = *(const int4*)&jl[t];
            float4 e0 = __ldcs(&Ep1[(size_t)j4.x * H4]);
            float4 e1 = __ldcs(&Ep1[(size_t)j4.y * H4]);
            float4 e2 = __ldcs(&Ep1[(size_t)j4.z * H4]);
            float4 e3 = __ldcs(&Ep1[(size_t)j4.w * H4]);
            float4 h0v = h0s[j4.x * H4 + hq];
            float4 h1v = h0s[j4.y * H4 + hq];
            float4 h2v = h0s[j4.z * H4 + hq];
            float4 h3v = h0s[j4.w * H4 + hq];
            acc.x = fmaxf(acc.x, e0.x * h0v.x); acc.y = fmaxf(acc.y, e0.y * h0v.y);
            acc.z = fmaxf(acc.z, e0.z * h0v.z); acc.w = fmaxf(acc.w, e0.w * h0v.w);
            acc.x = fmaxf(acc.x, e1.x * h1v.x); acc.y = fmaxf(acc.y, e1.y * h1v.y);
            acc.z = fmaxf(acc.z, e1.z * h1v.z); acc.w = fmaxf(acc.w, e1.w * h1v.w);
            acc.x = fmaxf(acc.x, e2.x * h2v.x); acc.y = fmaxf(acc.y, e2.y * h2v.y);
            acc.z = fmaxf(acc.z, e2.z * h2v.z); acc.w = fmaxf(acc.w, e2.w * h2v.w);
            acc.x = fmaxf(acc.x, e3.x * h3v.x); acc.y = fmaxf(acc.y, e3.y * h3v.y);
            acc.z = fmaxf(acc.z, e3.z * h3v.z); acc.w = fmaxf(acc.w, e3.w * h3v.w);
        }
        for (; t < c1; t++) {
            const int j = jl[t];
            float4 ev = __ldcs(&Ep1[(size_t)j * H4]);
            float4 hv = h0s[j * H4 + hq];
            acc.x = fmaxf(acc.x, ev.x * hv.x);
            acc.y = fmaxf(acc.y, ev.y * hv.y);
            acc.z = fmaxf(acc.z, ev.z * hv.z);
            acc.w = fmaxf(acc.w, ev.w * hv.w);
        }
    }

    if (c0 + c1 < 128) {                  // masked rows contribute exactly 0
        acc.x = fmaxf(acc.x, 0.0f);
        acc.y = fmaxf(acc.y, 0.0f);
        acc.z = fmaxf(acc.z, 0.0f);
        acc.w = fmaxf(acc.w, 0.0f);
    }

    ((float4*)g_part)[((size_t)jh * ROWS + b * Vv + i) * H4 + hq] = acc;
}

// ---------------------------------------------------------------------------
// Kernel C: out = silu( sk + silu([h0,neigh] @ W_post + b_post) )
// 2-D tiled: 512 blocks (128 row-tiles x 4 col-tiles) x 128 threads. (frozen)
// ---------------------------------------------------------------------------
extern __shared__ float s_dyn[];

__global__ void __launch_bounds__(128) post_kernel(
    const float* __restrict__ Wpost, const float* __restrict__ bpost,
    float* __restrict__ out)
{
    float* sW = s_dyn;                    // sW[k][c], 256 x 32
    float* aT = s_dyn + 2 * Hv * 32;      // aT[k][r], 256 x 16

    const int tid  = threadIdx.x;
    const int c    = tid & 31;
    const int rg   = tid >> 5;            // 0..3
    const int rowT = blockIdx.x >> 2;
    const int colT = blockIdx.x & 3;
    const int row0 = rowT * 16;
    const int col0 = colT * 32;

    const float4* Wg = (const float4*)Wpost;
#pragma unroll
    for (int r = 0; r < 16; r++) {
        const int x = r * 128 + tid;           // x = k*8 + c4
        ((float4*)sW)[x] = Wg[(x >> 3) * 32 + colT * 8 + (x & 7)];
    }

    const float4* h04 = (const float4*)g_h0;
    const float4* gp  = (const float4*)g_part;
#pragma unroll
    for (int x = tid; x < 512; x += 128) {
        const int rr = x & 15, k4 = x >> 4;
        float4 v = h04[(row0 + rr) * H4 + k4];
        aT[(k4 * 4 + 0) * 16 + rr] = v.x;
        aT[(k4 * 4 + 1) * 16 + rr] = v.y;
        aT[(k4 * 4 + 2) * 16 + rr] = v.z;
        aT[(k4 * 4 + 3) * 16 + rr] = v.w;
        float4 p0 = gp[(row0 + rr) * H4 + k4];
        float4 p1 = gp[(size_t)ROWS * H4 + (row0 + rr) * H4 + k4];
        aT[(Hv + k4 * 4 + 0) * 16 + rr] = fmaxf(p0.x, p1.x);
        aT[(Hv + k4 * 4 + 1) * 16 + rr] = fmaxf(p0.y, p1.y);
        aT[(Hv + k4 * 4 + 2) * 16 + rr] = fmaxf(p0.z, p1.z);
        aT[(Hv + k4 * 4 + 3) * 16 + rr] = fmaxf(p0.w, p1.w);
    }
    __syncthreads();

    ull acc0, acc1;
    {
        const float bP = bpost[col0 + c];
        acc0 = pack2(bP, bP);
        acc1 = pack2(0.f, 0.f);
    }

#pragma unroll 16
    for (int k = 0; k < 2 * Hv; k++) {
        ulonglong2 av = *(const ulonglong2*)&aT[k * 16 + 4 * rg];  // 4 rows, bcast
        const float w = sW[k * 32 + c];
        const ull w2 = pack2(w, w);
        acc0 = ffma2(av.x, w2, acc0);
        acc1 = ffma2(av.y, w2, acc1);
    }

    {
        float2 v0 = unpack2(acc0), v1 = unpack2(acc1);
        const int row = row0 + 4 * rg;
        const int col = col0 + c;
        out[(row + 0) * Hv + col] = silu_f(g_sk[(row + 0) * Hv + col] + silu_f(v0.x));
        out[(row + 1) * Hv + col] = silu_f(g_sk[(row + 1) * Hv + col] + silu_f(v0.y));
        out[(row + 2) * Hv + col] = silu_f(g_sk[(row + 2) * Hv + col] + silu_f(v1.x));
        out[(row + 3) * Hv + col] = silu_f(g_sk[(row + 3) * Hv + col] + silu_f(v1.y));
    }
}

// ---------------------------------------------------------------------------
extern "C" void kernel_launch(void* const* d_in, const int* in_sizes, int n_in,
                              void* d_out, int out_size)
{
    const float* h     = (const float*)d_in[0];
    const float* e     = (const float*)d_in[1];
    const int*   graph = (const int*)  d_in[2];
    const float* Wpre  = (const float*)d_in[3];
    const float* bpre  = (const float*)d_in[4];
    const float* Wpost = (const float*)d_in[5];
    const float* bpost = (const float*)d_in[6];
    const float* Wskip = (const float*)d_in[7];
    const float* bskip = (const float*)d_in[8];
    float* out = (float*)d_out;

    const int postSmem = (2 * Hv * 32 + 2 * Hv * 16) * 4;     // 48 KB
    cudaFuncSetAttribute(post_kernel, cudaFuncAttributeMaxDynamicSharedMemorySize, postSmem);

    pre_kernel<<<512, 128>>>(h, Wpre, bpre, Wskip, bskip);
    agg_kernel<<<(ROWS / 8) * 2, 256>>>(e, graph);
    post_kernel<<<512, 128, postSmem>>>(Wpost, bpost, out);
}